// round 11
// baseline (speedup 1.0000x reference)
#include <cuda_runtime.h>

// Shapes fixed by the dataset: B=16, T=12 -> BT=192, N=512, Fin=Fout=64.
#define NN   512
#define FF   64
#define BTMAX 192

// Scratch (device globals: allocation-free per harness rules)
__device__ float    g_Wh [(size_t)BTMAX * NN * FF];   // [bt][n][o]
__device__ float    g_Wh1[(size_t)BTMAX * NN];
__device__ float    g_Wh2[(size_t)BTMAX * NN];
__device__ unsigned g_mask[NN * 16];                  // 512 rows x 16 words of adjacency bits

// Fast exp(x) for x <= 0 (clamped), poly-exp2 on fma/alu pipes (avoids MUFU bottleneck).
__device__ __forceinline__ float fexp(float x) {
    x = fmaxf(x, -87.0f);
    float t  = x * 1.4426950408889634f;          // log2(e)
    float fi = t + 12582912.0f;                  // round-to-nearest via magic
    int   i  = __float_as_int(fi) - 0x4B400000;  // integer part
    float f  = t - (fi - 12582912.0f);           // frac in [-0.5, 0.5]
    float p  = 1.3333558146e-3f;
    p = fmaf(p, f, 9.6181291076e-3f);
    p = fmaf(p, f, 5.5504108664e-2f);
    p = fmaf(p, f, 2.4022650695e-1f);
    p = fmaf(p, f, 6.9314718056e-1f);
    p = fmaf(p, f, 1.0f);                        // ~2^f
    return __int_as_float(__float_as_int(p) + (i << 23));
}

// ---------------------------------------------------------------------------
// Kernel 0: adjacency (512x512 float) -> bitmask (512x16 uint32)
// ---------------------------------------------------------------------------
__global__ void k_mask(const float* __restrict__ adj) {
    int w = blockIdx.x * blockDim.x + threadIdx.x;   // 0..8191
    int row = w >> 4, wi = w & 15;
    const float* arow = adj + row * NN + wi * 32;
    unsigned m = 0;
#pragma unroll
    for (int b = 0; b < 32; ++b)
        if (arow[b] > 0.f) m |= (1u << b);
    g_mask[w] = m;
}

// ---------------------------------------------------------------------------
// Kernel 1: Wh = h @ W (per bt), plus Wh1 = Wh@a1, Wh2 = Wh@a2.
// Grid (8, BT), 256 threads, 64-row tiles, 4x4 register tiling.
// ---------------------------------------------------------------------------
__global__ void __launch_bounds__(256)
k_wh(const float* __restrict__ h, const float* __restrict__ W,
     const float* __restrict__ a) {
    __shared__ float h_s[64 * 68];    // [k][r], pad 68 for bank behavior + f4 align
    __shared__ float W_s[64 * 64];    // [k][o]
    __shared__ float a_s[128];

    const int bt = blockIdx.y;
    const int i0 = blockIdx.x * 64;
    const int tid = threadIdx.x;

    const float* hg = h + ((size_t)bt * NN + i0) * FF;
    for (int e = tid; e < 4096; e += 256) {
        int r = e >> 6, k = e & 63;
        h_s[k * 68 + r] = hg[e];
    }
    for (int e = tid; e < 4096; e += 256) W_s[e] = W[e];
    if (tid < 128) a_s[tid] = a[tid];
    __syncthreads();

    const int to = tid & 15;        // o-quad
    const int ti = tid >> 4;        // row-quad
    float acc[4][4] = {};
#pragma unroll 8
    for (int k = 0; k < 64; ++k) {
        float4 hv = *(const float4*)&h_s[k * 68 + 4 * ti];
        float4 wv = *(const float4*)&W_s[k * 64 + 4 * to];
        acc[0][0] = fmaf(hv.x, wv.x, acc[0][0]); acc[0][1] = fmaf(hv.x, wv.y, acc[0][1]);
        acc[0][2] = fmaf(hv.x, wv.z, acc[0][2]); acc[0][3] = fmaf(hv.x, wv.w, acc[0][3]);
        acc[1][0] = fmaf(hv.y, wv.x, acc[1][0]); acc[1][1] = fmaf(hv.y, wv.y, acc[1][1]);
        acc[1][2] = fmaf(hv.y, wv.z, acc[1][2]); acc[1][3] = fmaf(hv.y, wv.w, acc[1][3]);
        acc[2][0] = fmaf(hv.z, wv.x, acc[2][0]); acc[2][1] = fmaf(hv.z, wv.y, acc[2][1]);
        acc[2][2] = fmaf(hv.z, wv.z, acc[2][2]); acc[2][3] = fmaf(hv.z, wv.w, acc[2][3]);
        acc[3][0] = fmaf(hv.w, wv.x, acc[3][0]); acc[3][1] = fmaf(hv.w, wv.y, acc[3][1]);
        acc[3][2] = fmaf(hv.w, wv.z, acc[3][2]); acc[3][3] = fmaf(hv.w, wv.w, acc[3][3]);
    }

    float* og = g_Wh + ((size_t)bt * NN + i0) * FF;
#pragma unroll
    for (int r = 0; r < 4; ++r) {
        float4 v = make_float4(acc[r][0], acc[r][1], acc[r][2], acc[r][3]);
        *(float4*)&og[(4 * ti + r) * FF + 4 * to] = v;
    }

    // Wh1/Wh2 per-row dot with a1/a2: reduce over the 16 o-quads (lanes 0..15 of each half-warp)
    float a1v0 = a_s[4 * to], a1v1 = a_s[4 * to + 1], a1v2 = a_s[4 * to + 2], a1v3 = a_s[4 * to + 3];
    float a2v0 = a_s[64 + 4 * to], a2v1 = a_s[64 + 4 * to + 1],
          a2v2 = a_s[64 + 4 * to + 2], a2v3 = a_s[64 + 4 * to + 3];
#pragma unroll
    for (int r = 0; r < 4; ++r) {
        float s1 = acc[r][0] * a1v0 + acc[r][1] * a1v1 + acc[r][2] * a1v2 + acc[r][3] * a1v3;
        float s2 = acc[r][0] * a2v0 + acc[r][1] * a2v1 + acc[r][2] * a2v2 + acc[r][3] * a2v3;
#pragma unroll
        for (int off = 8; off; off >>= 1) {
            s1 += __shfl_down_sync(0xffffffffu, s1, off, 16);
            s2 += __shfl_down_sync(0xffffffffu, s2, off, 16);
        }
        if (to == 0) {
            g_Wh1[(size_t)bt * NN + i0 + 4 * ti + r] = s1;
            g_Wh2[(size_t)bt * NN + i0 + 4 * ti + r] = s2;
        }
    }
}

// ---------------------------------------------------------------------------
// Kernel 2: fused attention. Grid (8, BT), 256 threads.
// Per CTA: rows [i0, i0+64) of one (b,t). Exact softmax max via monotone
// lrelu + masked max of Wh2 (precomputed per row), then single pass:
// P tile (64x64) -> shared, 4x4-register-tiled P @ Wh_j GEMM, ELU epilogue.
// ---------------------------------------------------------------------------
__global__ void __launch_bounds__(256)
k_attn(float* __restrict__ out) {
    __shared__ float    wh2s[NN];           // 2 KB
    __shared__ float    wh1s[64];
    __shared__ float    ms[64];
    __shared__ float    lrs[64];
    __shared__ float    lps[256];
    __shared__ unsigned mask_s[64 * 17];    // padded stride 17 (conflict-free)
    __shared__ float    Ps[64 * 64];        // [j][i]
    __shared__ float    Whjs[64 * 64];      // [j][o]

    const int bt = blockIdx.y;
    const int i0 = blockIdx.x * 64;
    const int tid = threadIdx.x;

    for (int e = tid; e < NN; e += 256) wh2s[e] = g_Wh2[(size_t)bt * NN + e];
    if (tid < 64) wh1s[tid] = g_Wh1[(size_t)bt * NN + i0 + tid];
    for (int w = tid; w < 1024; w += 256) {
        int r = w >> 4, c = w & 15;
        mask_s[r * 17 + c] = g_mask[(i0 + r) * 16 + c];
    }
    __syncthreads();

    // --- per-row softmax max: m_i = lrelu(Wh1_i + max_{j in adj(i)} Wh2_j) ---
    {
        int r = tid >> 2, q = tid & 3;     // 4 lanes per row
        float vmax = -1e30f;
#pragma unroll
        for (int w = 0; w < 4; ++w) {
            unsigned word = mask_s[r * 17 + q * 4 + w];
            int jb = (q * 4 + w) * 32;
#pragma unroll
            for (int b = 0; b < 32; ++b)
                if (word & (1u << b)) vmax = fmaxf(vmax, wh2s[jb + b]);
        }
        vmax = fmaxf(vmax, __shfl_xor_sync(0xffffffffu, vmax, 1, 4));
        vmax = fmaxf(vmax, __shfl_xor_sync(0xffffffffu, vmax, 2, 4));
        if (q == 0) {
            float s = wh1s[r] + vmax;
            ms[r] = (vmax < -1e29f) ? 0.f : (s > 0.f ? s : 0.2f * s);
        }
    }
    __syncthreads();

    const int pi = tid & 63, pg = tid >> 6;       // P-phase mapping
    const int i4 = tid >> 4, to = tid & 15;       // GEMM mapping
    const float w1   = wh1s[pi];
    const float mrow = ms[pi];

    float acc[4][4] = {};
    float lp = 0.f;

    for (int jt = 0; jt < 8; ++jt) {
        // stage Wh_j tile to registers (hide LDG latency under P compute)
        const float4* src = (const float4*)(g_Wh + ((size_t)bt * NN + jt * 64) * FF);
        float4 st0 = src[tid], st1 = src[tid + 256], st2 = src[tid + 512], st3 = src[tid + 768];

        // P phase: each thread computes 16 p's for row pi, j-group pg
        unsigned word = mask_s[pi * 17 + jt * 2 + (pg >> 1)];
        int sh = (pg & 1) * 16;
#pragma unroll
        for (int jj = 0; jj < 16; ++jj) {
            int j = jt * 64 + pg * 16 + jj;
            float s  = w1 + wh2s[j];
            float ev = s > 0.f ? s : 0.2f * s;
            float p  = ((word >> (sh + jj)) & 1u) ? fexp(ev - mrow) : 0.f;
            Ps[(pg * 16 + jj) * 64 + pi] = p;
            lp += p;
        }
        ((float4*)Whjs)[tid]       = st0;
        ((float4*)Whjs)[tid + 256] = st1;
        ((float4*)Whjs)[tid + 512] = st2;
        ((float4*)Whjs)[tid + 768] = st3;
        __syncthreads();

        // GEMM: acc[64i x 64o] += P(64x64) @ Whj(64x64)
#pragma unroll 8
        for (int jj = 0; jj < 64; ++jj) {
            float4 pv = *(const float4*)&Ps[jj * 64 + 4 * i4];
            float4 wv = *(const float4*)&Whjs[jj * 64 + 4 * to];
            acc[0][0] = fmaf(pv.x, wv.x, acc[0][0]); acc[0][1] = fmaf(pv.x, wv.y, acc[0][1]);
            acc[0][2] = fmaf(pv.x, wv.z, acc[0][2]); acc[0][3] = fmaf(pv.x, wv.w, acc[0][3]);
            acc[1][0] = fmaf(pv.y, wv.x, acc[1][0]); acc[1][1] = fmaf(pv.y, wv.y, acc[1][1]);
            acc[1][2] = fmaf(pv.y, wv.z, acc[1][2]); acc[1][3] = fmaf(pv.y, wv.w, acc[1][3]);
            acc[2][0] = fmaf(pv.z, wv.x, acc[2][0]); acc[2][1] = fmaf(pv.z, wv.y, acc[2][1]);
            acc[2][2] = fmaf(pv.z, wv.z, acc[2][2]); acc[2][3] = fmaf(pv.z, wv.w, acc[2][3]);
            acc[3][0] = fmaf(pv.w, wv.x, acc[3][0]); acc[3][1] = fmaf(pv.w, wv.y, acc[3][1]);
            acc[3][2] = fmaf(pv.w, wv.z, acc[3][2]); acc[3][3] = fmaf(pv.w, wv.w, acc[3][3]);
        }
        __syncthreads();
    }

    // reduce l_i across the 4 j-groups
    lps[tid] = lp;
    __syncthreads();
    if (tid < 64) {
        float l = lps[tid] + lps[tid + 64] + lps[tid + 128] + lps[tid + 192];
        lrs[tid] = (l > 0.f) ? 1.f / l : 0.f;
    }
    __syncthreads();

    // epilogue: normalize + ELU, coalesced float4 stores
    float* og = out + ((size_t)bt * NN + i0) * FF;
#pragma unroll
    for (int r = 0; r < 4; ++r) {
        int i = 4 * i4 + r;
        float inv = lrs[i];
        float v0 = acc[r][0] * inv, v1 = acc[r][1] * inv,
              v2 = acc[r][2] * inv, v3 = acc[r][3] * inv;
        v0 = v0 > 0.f ? v0 : fexp(v0) - 1.f;
        v1 = v1 > 0.f ? v1 : fexp(v1) - 1.f;
        v2 = v2 > 0.f ? v2 : fexp(v2) - 1.f;
        v3 = v3 > 0.f ? v3 : fexp(v3) - 1.f;
        *(float4*)&og[i * FF + 4 * to] = make_float4(v0, v1, v2, v3);
    }
}

// ---------------------------------------------------------------------------
extern "C" void kernel_launch(void* const* d_in, const int* in_sizes, int n_in,
                              void* d_out, int out_size) {
    const float* h   = (const float*)d_in[0];
    const float* adj = (const float*)d_in[1];
    const float* W   = (const float*)d_in[2];
    const float* a   = (const float*)d_in[3];
    int BT = in_sizes[0] / (NN * FF);   // 192 for this dataset

    k_mask<<<32, 256>>>(adj);
    k_wh  <<<dim3(8, BT), 256>>>(h, W, a);
    k_attn<<<dim3(8, BT), 256>>>((float*)d_out);
}